// round 1
// baseline (speedup 1.0000x reference)
#include <cuda_runtime.h>

#define NN 1024
#define EE 2048
#define CIN 4
#define HID 192
#define KCH 5
#define NL 4
#define KAUG (5*HID)   // 960

// ---------------- device scratch (allocation-free) ----------------
__device__ float g_deg[NN];
__device__ float g_dinv[NN];
__device__ float g_wnorm[EE];
__device__ float g_Tx[KCH][NN][CIN];
__device__ float g_h[NN*HID];
__device__ float g_z[NN*HID];
__device__ float g_agg[NN*HID];
__device__ float g_G[NL][5][HID];          // rows 0..3: G[c] = eenc_w@nn1_w ; row 4: g0
__device__ float g_M[NL][KAUG*HID];        // Mstack per layer: [(k*HID+i)][o]

// ---------------- small prep kernels ----------------
__global__ void k_zero_deg() {
    int t = blockIdx.x*blockDim.x + threadIdx.x;
    if (t < NN) g_deg[t] = 0.f;
}
__global__ void k_deg(const int* __restrict__ ei) {
    int e = blockIdx.x*blockDim.x + threadIdx.x;
    if (e < EE) atomicAdd(&g_deg[ei[e]], 1.f);
}
__global__ void k_dinv() {
    int t = blockIdx.x*blockDim.x + threadIdx.x;
    if (t < NN) g_dinv[t] = g_deg[t] > 0.f ? 1.f / sqrtf(g_deg[t]) : 0.f;
}
__global__ void k_wnorm(const int* __restrict__ ei) {
    int e = blockIdx.x*blockDim.x + threadIdx.x;
    if (e < EE) g_wnorm[e] = -g_dinv[ei[e]] * g_dinv[ei[EE+e]];
}
__global__ void k_tx0(const float* __restrict__ x) {
    int t = blockIdx.x*blockDim.x + threadIdx.x;
    if (t < NN*CIN) ((float*)g_Tx)[t] = x[t];
}
__global__ void k_cheb_init(int k) {
    int t = blockIdx.x*blockDim.x + threadIdx.x;
    if (t >= NN*CIN) return;
    int n = t >> 2, c = t & 3;
    g_Tx[k][n][c] = (k == 1) ? 0.f : -g_Tx[k-2][n][c];
}
__global__ void k_cheb_scatter(const int* __restrict__ ei, int k) {
    int t = blockIdx.x*blockDim.x + threadIdx.x;
    if (t >= EE*CIN) return;
    int e = t >> 2, c = t & 3;
    float w = g_wnorm[e] * (k >= 2 ? 2.f : 1.f);
    atomicAdd(&g_Tx[k][ei[EE+e]][c], w * g_Tx[k-1][ei[e]][c]);
}
__global__ void k_cheb_out(const float* __restrict__ cheb_w, const float* __restrict__ cheb_b) {
    int n = blockIdx.x, o = threadIdx.x;   // 1024 blocks x 192 threads
    float acc = cheb_b[o];
    #pragma unroll
    for (int k = 0; k < KCH; k++)
        #pragma unroll
        for (int c = 0; c < CIN; c++)
            acc += g_Tx[k][n][c] * cheb_w[(k*CIN + c)*HID + o];
    g_h[n*HID + o] = acc;
}

// ---------------- edge-MLP linearization precompute ----------------
// G[c,j] = sum_j0 eenc_w[c,j0]*nn1_w[i][j0,j];  g0[j] = sum_j0 eenc_b[j0]*nn1_w[i][j0,j] + nn1_b[i][j]
__global__ void k_G(const float* __restrict__ eenc_w, const float* __restrict__ eenc_b,
                    const float* __restrict__ nn1_w, const float* __restrict__ nn1_b) {
    int i = blockIdx.x;        // layer
    int j = threadIdx.x;       // 192
    float acc[5] = {0.f, 0.f, 0.f, 0.f, 0.f};
    const float* W = nn1_w + i*HID*HID;
    for (int j0 = 0; j0 < HID; j0++) {
        float w = W[j0*HID + j];
        #pragma unroll
        for (int c = 0; c < CIN; c++) acc[c] += eenc_w[c*HID + j0] * w;
        acc[4] += eenc_b[j0] * w;
    }
    acc[4] += nn1_b[i*HID + j];
    #pragma unroll
    for (int k = 0; k < 5; k++) g_G[i][k][j] = acc[k];
}

// Mstack[i][(k*HID+i2)*HID + o] : k<4 -> Weff[k, i2*H+o] ; k=4 -> beff[i2*H+o]
__global__ void k_M(const float* __restrict__ nn2_w, const float* __restrict__ nn2_b) {
    int i = blockIdx.y;
    int m = blockIdx.x*256 + threadIdx.x;   // 0..36863
    __shared__ float sG[5*HID];
    for (int q = threadIdx.x; q < 5*HID; q += 256) sG[q] = ((const float*)g_G[i])[q];
    __syncthreads();
    const float* W = nn2_w + (size_t)i * HID * HID * HID;   // [192, 36864] row-major
    float acc[5] = {0.f, 0.f, 0.f, 0.f, 0.f};
    for (int j = 0; j < HID; j++) {
        float w = W[(size_t)j * (HID*HID) + m];
        #pragma unroll
        for (int k = 0; k < 5; k++) acc[k] += sG[k*HID + j] * w;
    }
    acc[4] += nn2_b[(size_t)i * (HID*HID) + m];
    int i2 = m / HID;
    int o  = m - i2 * HID;
    #pragma unroll
    for (int k = 0; k < 5; k++) g_M[i][(k*HID + i2)*HID + o] = acc[k];
}

// ---------------- LayerNorm + ReLU ----------------
__global__ void k_ln_relu(const float* __restrict__ g, const float* __restrict__ b) {
    int n = blockIdx.x, t = threadIdx.x;    // 1024 x 192
    __shared__ float red[6];
    float v = g_h[n*HID + t];
    float s = v;
    #pragma unroll
    for (int o = 16; o > 0; o >>= 1) s += __shfl_xor_sync(0xffffffffu, s, o);
    if ((t & 31) == 0) red[t >> 5] = s;
    __syncthreads();
    float tot = 0.f;
    #pragma unroll
    for (int w = 0; w < 6; w++) tot += red[w];
    float mu = tot * (1.f/192.f);
    float d = v - mu;
    float s2 = d * d;
    #pragma unroll
    for (int o = 16; o > 0; o >>= 1) s2 += __shfl_xor_sync(0xffffffffu, s2, o);
    __syncthreads();
    if ((t & 31) == 0) red[t >> 5] = s2;
    __syncthreads();
    float var = 0.f;
    #pragma unroll
    for (int w = 0; w < 6; w++) var += red[w];
    var *= (1.f/192.f);
    g_z[n*HID + t] = fmaxf(0.f, d * rsqrtf(var + 1e-5f) * g[t] + b[t]);
}

// ---------------- root GEMM: agg = z @ root_w[i] + conv_b[i] ----------------
// M=1024, N=192, K=192.  BM=64, BN=64, BK=32, 256 threads, 4x4 per thread.
__global__ void __launch_bounds__(256)
k_gemm_root(int useH, const float* __restrict__ rw, const float* __restrict__ cb) {
    __shared__ float sA[32*65];
    __shared__ float sB[32*65];
    const float* z = useH ? g_h : g_z;
    int t = threadIdx.x;
    int m0 = blockIdx.x * 64;
    int n0 = blockIdx.y * 64;
    int ty = t >> 4, tx = t & 15;
    float acc[4][4] = {};
    for (int kt = 0; kt < HID/32; kt++) {
        int kk0 = kt * 32;
        #pragma unroll
        for (int r = 0; r < 2; r++) {
            int q = t + r*256;
            int e = q >> 3, f4 = q & 7;
            float4 v = *(const float4*)(z + (m0 + e)*HID + kk0 + f4*4);
            sA[(f4*4+0)*65 + e] = v.x;
            sA[(f4*4+1)*65 + e] = v.y;
            sA[(f4*4+2)*65 + e] = v.z;
            sA[(f4*4+3)*65 + e] = v.w;
        }
        #pragma unroll
        for (int r = 0; r < 2; r++) {
            int q = t + r*256;
            int kk = q >> 4, c4 = q & 15;
            float4 v = *(const float4*)(rw + (kk0 + kk)*HID + n0 + c4*4);
            sB[kk*65 + c4*4+0] = v.x;
            sB[kk*65 + c4*4+1] = v.y;
            sB[kk*65 + c4*4+2] = v.z;
            sB[kk*65 + c4*4+3] = v.w;
        }
        __syncthreads();
        #pragma unroll
        for (int kk = 0; kk < 32; kk++) {
            float a0 = sA[kk*65 + ty*4+0], a1 = sA[kk*65 + ty*4+1];
            float a2 = sA[kk*65 + ty*4+2], a3 = sA[kk*65 + ty*4+3];
            float b0 = sB[kk*65 + tx*4+0], b1 = sB[kk*65 + tx*4+1];
            float b2 = sB[kk*65 + tx*4+2], b3 = sB[kk*65 + tx*4+3];
            acc[0][0] += a0*b0; acc[0][1] += a0*b1; acc[0][2] += a0*b2; acc[0][3] += a0*b3;
            acc[1][0] += a1*b0; acc[1][1] += a1*b1; acc[1][2] += a1*b2; acc[1][3] += a1*b3;
            acc[2][0] += a2*b0; acc[2][1] += a2*b1; acc[2][2] += a2*b2; acc[2][3] += a2*b3;
            acc[3][0] += a3*b0; acc[3][1] += a3*b1; acc[3][2] += a3*b2; acc[3][3] += a3*b3;
        }
        __syncthreads();
    }
    #pragma unroll
    for (int p = 0; p < 4; p++)
        #pragma unroll
        for (int q = 0; q < 4; q++)
            g_agg[(m0 + ty*4 + p)*HID + n0 + tx*4 + q] = acc[p][q] + cb[n0 + tx*4 + q];
}

// ---------------- fused msg GEMM + scatter ----------------
// msg[E,192] = A[E,960] @ Mstack[960,192],  A[e, k*192+i] = coef_k(e)*z[src[e],i]
// epilogue: atomicAdd into g_agg[dst[e]][o]
__global__ void __launch_bounds__(256)
k_gemm_msg(int layer, int useH, const float* __restrict__ attr, const int* __restrict__ ei) {
    __shared__ float sA[32*65];
    __shared__ float sB[32*65];
    __shared__ int   sSrc[64];
    __shared__ int   sDst[64];
    __shared__ float sCoef[64*5];
    const float* z  = useH ? g_h : g_z;
    const float* Mw = g_M[layer];
    int t = threadIdx.x;
    int m0 = blockIdx.x * 64;
    int n0 = blockIdx.y * 64;
    if (t < 64) {
        int e = m0 + t;
        sSrc[t] = ei[e];
        sDst[t] = ei[EE + e];
        #pragma unroll
        for (int c = 0; c < 4; c++) sCoef[t*5 + c] = attr[e*4 + c];
        sCoef[t*5 + 4] = 1.f;
    }
    int ty = t >> 4, tx = t & 15;
    float acc[4][4] = {};
    __syncthreads();
    for (int kt = 0; kt < KAUG/32; kt++) {
        int kk0 = kt * 32;
        int kc  = kk0 / HID;          // constant within tile (192 = 6*32)
        int ib  = kk0 - kc * HID;
        #pragma unroll
        for (int r = 0; r < 2; r++) {
            int q = t + r*256;
            int e = q >> 3, f4 = q & 7;
            float4 v = *(const float4*)(z + sSrc[e]*HID + ib + f4*4);
            float cf = sCoef[e*5 + kc];
            sA[(f4*4+0)*65 + e] = v.x * cf;
            sA[(f4*4+1)*65 + e] = v.y * cf;
            sA[(f4*4+2)*65 + e] = v.z * cf;
            sA[(f4*4+3)*65 + e] = v.w * cf;
        }
        #pragma unroll
        for (int r = 0; r < 2; r++) {
            int q = t + r*256;
            int kk = q >> 4, c4 = q & 15;
            float4 v = *(const float4*)(Mw + (kk0 + kk)*HID + n0 + c4*4);
            sB[kk*65 + c4*4+0] = v.x;
            sB[kk*65 + c4*4+1] = v.y;
            sB[kk*65 + c4*4+2] = v.z;
            sB[kk*65 + c4*4+3] = v.w;
        }
        __syncthreads();
        #pragma unroll
        for (int kk = 0; kk < 32; kk++) {
            float a0 = sA[kk*65 + ty*4+0], a1 = sA[kk*65 + ty*4+1];
            float a2 = sA[kk*65 + ty*4+2], a3 = sA[kk*65 + ty*4+3];
            float b0 = sB[kk*65 + tx*4+0], b1 = sB[kk*65 + tx*4+1];
            float b2 = sB[kk*65 + tx*4+2], b3 = sB[kk*65 + tx*4+3];
            acc[0][0] += a0*b0; acc[0][1] += a0*b1; acc[0][2] += a0*b2; acc[0][3] += a0*b3;
            acc[1][0] += a1*b0; acc[1][1] += a1*b1; acc[1][2] += a1*b2; acc[1][3] += a1*b3;
            acc[2][0] += a2*b0; acc[2][1] += a2*b1; acc[2][2] += a2*b2; acc[2][3] += a2*b3;
            acc[3][0] += a3*b0; acc[3][1] += a3*b1; acc[3][2] += a3*b2; acc[3][3] += a3*b3;
        }
        __syncthreads();
    }
    #pragma unroll
    for (int p = 0; p < 4; p++) {
        int d = sDst[ty*4 + p];
        #pragma unroll
        for (int q = 0; q < 4; q++)
            atomicAdd(&g_agg[d*HID + n0 + tx*4 + q], acc[p][q]);
    }
}

// ---------------- h update ----------------
__global__ void k_update(int residual) {
    int t = blockIdx.x*blockDim.x + threadIdx.x;
    if (t >= NN*HID) return;
    g_h[t] = residual ? (g_h[t] + g_agg[t]) : g_agg[t];
}

// ---------------- final linear (uses g_z = relu(ln0(h))) ----------------
__global__ void k_out(const float* __restrict__ ow, const float* __restrict__ ob,
                      float* __restrict__ out) {
    int t = blockIdx.x*blockDim.x + threadIdx.x;
    if (t >= NN*2) return;
    int n = t >> 1, oc = t & 1;
    float acc = ob[oc];
    for (int j = 0; j < HID; j++)
        acc += g_z[n*HID + j] * ow[j*2 + oc];
    out[n*2 + oc] = acc;
}

// ---------------- launcher ----------------
extern "C" void kernel_launch(void* const* d_in, const int* in_sizes, int n_in,
                              void* d_out, int out_size) {
    const float* x       = (const float*)d_in[0];
    const int*   ei      = (const int*)  d_in[1];
    const float* attr    = (const float*)d_in[2];
    const float* cheb_w  = (const float*)d_in[4];
    const float* cheb_b  = (const float*)d_in[5];
    const float* eenc_w  = (const float*)d_in[6];
    const float* eenc_b  = (const float*)d_in[7];
    const float* nn1_w   = (const float*)d_in[8];
    const float* nn1_b   = (const float*)d_in[9];
    const float* nn2_w   = (const float*)d_in[10];
    const float* nn2_b   = (const float*)d_in[11];
    const float* root_w  = (const float*)d_in[12];
    const float* conv_b  = (const float*)d_in[13];
    const float* ln_g    = (const float*)d_in[14];
    const float* ln_b    = (const float*)d_in[15];
    const float* out_w   = (const float*)d_in[16];
    const float* out_b   = (const float*)d_in[17];
    float* out = (float*)d_out;

    // edge-MLP linearization (graph-independent; heaviest HBM pass: nn2_w once)
    k_G<<<NL, HID>>>(eenc_w, eenc_b, nn1_w, nn1_b);
    k_M<<<dim3(144, NL), 256>>>(nn2_w, nn2_b);

    // degree / normalization
    k_zero_deg<<<4, 256>>>();
    k_deg<<<8, 256>>>(ei);
    k_dinv<<<4, 256>>>();
    k_wnorm<<<8, 256>>>(ei);

    // ChebConv
    k_tx0<<<16, 256>>>(x);
    for (int k = 1; k < KCH; k++) {
        k_cheb_init<<<16, 256>>>(k);
        k_cheb_scatter<<<32, 256>>>(ei, k);
    }
    k_cheb_out<<<NN, HID>>>(cheb_w, cheb_b);

    // 4 NNConv layers
    for (int i = 0; i < NL; i++) {
        int useH = (i == 0) ? 1 : 0;
        if (i > 0) k_ln_relu<<<NN, HID>>>(ln_g + i*HID, ln_b + i*HID);
        k_gemm_root<<<dim3(16, 3), 256>>>(useH, root_w + (size_t)i*HID*HID, conv_b + i*HID);
        k_gemm_msg<<<dim3(32, 3), 256>>>(i, useH, attr, ei);
        k_update<<<768, 256>>>(i == 0 ? 0 : 1);
    }

    // final norm + head
    k_ln_relu<<<NN, HID>>>(ln_g, ln_b);
    k_out<<<8, 256>>>(out_w, out_b, out);
}

// round 3
// speedup vs baseline: 1.8765x; 1.8765x over previous
#include <cuda_runtime.h>

#define NN 1024
#define EE 2048
#define CIN 4
#define HID 192
#define KCH 5
#define NL 4
#define NAUG 1152          // 5*HID (edge basis) + HID (root)

typedef unsigned long long ull;

// ---------------- device scratch (allocation-free) ----------------
__device__ float g_deg[NN];
__device__ float g_dinv[NN];
__device__ float g_S[4][NN][CIN];     // scatter buffers S_k = lap(T_{k-1}), k=1..4
__device__ float g_h[NN*HID];
__device__ float g_z[NN*HID];
__device__ float g_Y[NN*NAUG];        // per-layer node GEMM output
__device__ float g_G[NL][5*HID];      // rows 0..3: eenc_w@nn1_w ; row 4: bias path
__device__ float g_B[NL][HID*NAUG];   // B[i][j*1152 + k*192 + o] (k<5: Weff, cols 960+: root)

// ---------------- f32x2 helpers ----------------
__device__ __forceinline__ void fma2(ull &c, ull a, ull b) {
    asm("fma.rn.f32x2 %0, %1, %2, %0;" : "+l"(c) : "l"(a), "l"(b));
}
__device__ __forceinline__ ull pk2(float a) {
    ull r; asm("mov.b64 %0, {%1, %1};" : "=l"(r) : "f"(a)); return r;
}
__device__ __forceinline__ float2 up2(ull a) {
    float2 f; asm("mov.b64 {%0, %1}, %2;" : "=f"(f.x), "=f"(f.y) : "l"(a)); return f;
}

// ---------------- prep: zero + degree + dinv ----------------
__global__ void k_zero() {
    int t = blockIdx.x*blockDim.x + threadIdx.x;
    if (t < NN) g_deg[t] = 0.f;
    int s = t - NN;
    if (s >= 0 && s < 4*NN*CIN) ((float*)g_S)[s] = 0.f;
}
__global__ void k_deg(const int* __restrict__ ei) {
    int e = blockIdx.x*blockDim.x + threadIdx.x;
    if (e < EE) atomicAdd(&g_deg[ei[e]], 1.f);
}
__global__ void k_dinv() {
    int t = blockIdx.x*blockDim.x + threadIdx.x;
    if (t < NN) g_dinv[t] = g_deg[t] > 0.f ? rsqrtf(g_deg[t]) : 0.f;
}

// ---------------- Cheb scatter: S_k = lap(T_{k-1}) (NO Chebyshev 2x here) ----------------
// T0=x, T1=S1, T2=2*S2-x, T3=2*S3-S1, T4=2*S4-2*S2+x
__global__ void k_scat(const int* __restrict__ ei, const float* __restrict__ x, int k) {
    int t = blockIdx.x*blockDim.x + threadIdx.x;
    if (t >= EE*CIN) return;
    int e = t >> 2, c = t & 3;
    int s = ei[e], d = ei[EE + e];
    float w = -g_dinv[s] * g_dinv[d];
    float v;
    if (k == 1)      v = x[s*CIN + c];                        // T0
    else if (k == 2) v = g_S[0][s][c];                        // T1
    else if (k == 3) v = 2.f*g_S[1][s][c] - x[s*CIN + c];     // T2
    else             v = 2.f*g_S[2][s][c] - g_S[0][s][c];     // T3
    atomicAdd(&g_S[k-1][d][c], w * v);
}

// ---------------- Cheb output: h = sum_k T_k @ W_k + b ----------------
__global__ void k_cheb_out(const float* __restrict__ x,
                           const float* __restrict__ cw, const float* __restrict__ cb) {
    int n = blockIdx.x, o = threadIdx.x;   // 1024 x 192
    __shared__ float tx[KCH][CIN];
    if (o < CIN) {
        float xv = x[n*CIN + o];
        float s1 = g_S[0][n][o], s2 = g_S[1][n][o], s3 = g_S[2][n][o], s4 = g_S[3][n][o];
        tx[0][o] = xv;
        tx[1][o] = s1;
        tx[2][o] = 2.f*s2 - xv;
        tx[3][o] = 2.f*s3 - s1;
        tx[4][o] = 2.f*s4 - 2.f*s2 + xv;
    }
    __syncthreads();
    float acc = cb[o];
    #pragma unroll
    for (int k = 0; k < KCH; k++)
        #pragma unroll
        for (int c = 0; c < CIN; c++)
            acc += tx[k][c] * cw[(k*CIN + c)*HID + o];
    g_h[n*HID + o] = acc;
    g_z[n*HID + o] = acc;   // layer-0 NNConv input
}

// ---------------- edge-MLP linearization: G = [eenc_w; eenc_b-path] @ nn1_w ----------------
__global__ void k_G(const float* __restrict__ eenc_w, const float* __restrict__ eenc_b,
                    const float* __restrict__ nn1_w, const float* __restrict__ nn1_b) {
    int i = blockIdx.x;        // layer
    int j = threadIdx.x;       // 192
    float acc[5] = {0.f, 0.f, 0.f, 0.f, 0.f};
    const float* W = nn1_w + i*HID*HID;
    for (int j0 = 0; j0 < HID; j0++) {
        float w = W[j0*HID + j];
        #pragma unroll
        for (int c = 0; c < CIN; c++) acc[c] += eenc_w[c*HID + j0] * w;
        acc[4] += eenc_b[j0] * w;
    }
    acc[4] += nn1_b[i*HID + j];
    #pragma unroll
    for (int k = 0; k < 5; k++) g_G[i][k*HID + j] = acc[k];
}

// ---------------- Mstack: g_B[i][j*1152 + k*192 + o] = (G @ nn2_w) ----------------
__global__ void __launch_bounds__(256) k_M(const float* __restrict__ nn2_w,
                                           const float* __restrict__ nn2_b) {
    int i = blockIdx.y;
    int m4 = (blockIdx.x*256 + threadIdx.x) * 4;   // 0..36860
    __shared__ float2 sG[5*HID];                   // packed (g,g)
    for (int q = threadIdx.x; q < 5*HID; q += 256) {
        float g = g_G[i][q];
        sG[q] = make_float2(g, g);
    }
    __syncthreads();
    const float* W = nn2_w + (size_t)i * HID * (HID*HID);
    ull acc[5][2] = {};
    #pragma unroll 4
    for (int j = 0; j < HID; j++) {
        float4 v = __ldg((const float4*)(W + (size_t)j*(HID*HID) + m4));
        ull v01, v23;
        asm("mov.b64 %0, {%1, %2};" : "=l"(v01) : "f"(v.x), "f"(v.y));
        asm("mov.b64 %0, {%1, %2};" : "=l"(v23) : "f"(v.z), "f"(v.w));
        #pragma unroll
        for (int k = 0; k < 5; k++) {
            ull gk = *(const ull*)&sG[k*HID + j];
            fma2(acc[k][0], gk, v01);
            fma2(acc[k][1], gk, v23);
        }
    }
    float4 b = __ldg((const float4*)(nn2_b + (size_t)i*(HID*HID) + m4));
    float2 a40 = up2(acc[4][0]), a41 = up2(acc[4][1]);
    a40.x += b.x; a40.y += b.y; a41.x += b.z; a41.y += b.w;
    int j2 = m4 / HID;
    int o  = m4 - j2 * HID;
    float* dst = g_B[i] + j2*NAUG + o;
    #pragma unroll
    for (int k = 0; k < 4; k++) {
        *(float2*)(dst + k*HID)     = up2(acc[k][0]);
        *(float2*)(dst + k*HID + 2) = up2(acc[k][1]);
    }
    *(float2*)(dst + 4*HID)     = a40;
    *(float2*)(dst + 4*HID + 2) = a41;
}

// ---------------- copy root_w into g_B cols 960..1151 ----------------
__global__ void k_root(const float* __restrict__ root_w) {
    int t = blockIdx.x*256 + threadIdx.x;          // NL*HID*HID/4 = 36864 float4
    if (t >= NL*HID*HID/4) return;
    int i = t / (HID*HID/4);
    int r = t - i*(HID*HID/4);
    int j = r / (HID/4);
    int o4 = (r - j*(HID/4)) * 4;
    float4 v = *(const float4*)(root_w + (size_t)i*HID*HID + j*HID + o4);
    *(float4*)(g_B[i] + j*NAUG + 5*HID + o4) = v;
}

// ---------------- LayerNorm + ReLU: z = relu(ln(h)) ----------------
__global__ void k_ln_relu(const float* __restrict__ g, const float* __restrict__ b) {
    int n = blockIdx.x, t = threadIdx.x;    // 1024 x 192
    __shared__ float red[6];
    float v = g_h[n*HID + t];
    float s = v;
    #pragma unroll
    for (int o = 16; o > 0; o >>= 1) s += __shfl_xor_sync(0xffffffffu, s, o);
    if ((t & 31) == 0) red[t >> 5] = s;
    __syncthreads();
    float tot = 0.f;
    #pragma unroll
    for (int w = 0; w < 6; w++) tot += red[w];
    float mu = tot * (1.f/192.f);
    float d = v - mu;
    float s2 = d * d;
    #pragma unroll
    for (int o = 16; o > 0; o >>= 1) s2 += __shfl_xor_sync(0xffffffffu, s2, o);
    __syncthreads();
    if ((t & 31) == 0) red[t >> 5] = s2;
    __syncthreads();
    float var = 0.f;
    #pragma unroll
    for (int w = 0; w < 6; w++) var += red[w];
    var *= (1.f/192.f);
    g_z[n*HID + t] = fmaxf(0.f, d * rsqrtf(var + 1e-5f) * g[t] + b[t]);
}

// ---------------- node GEMM: Y[1024,1152] = Z[1024,192] @ B[192,1152] ----------------
// BM=128, BN=64, BK=32, 256 threads, 8x4 per thread via fma.rn.f32x2.
// Epilogue: cols < 960 -> g_Y ; cols >= 960 (root) -> g_h = resid*h + acc + conv_b
__global__ void __launch_bounds__(256)
k_gemm(int layer, int resid, const float* __restrict__ cb) {
    __shared__ float sA[32*129];
    __shared__ float sB[32*68];
    const float* A = g_z;
    const float* B = g_B[layer];
    int t = threadIdx.x;
    int m0 = blockIdx.x * 128;
    int n0 = blockIdx.y * 64;
    int ty = t >> 4, tx = t & 15;
    ull acc[8][2] = {};
    #pragma unroll 1
    for (int kt = 0; kt < HID/32; kt++) {
        int k0 = kt * 32;
        #pragma unroll
        for (int r = 0; r < 4; r++) {
            int q = t + r*256;
            int e = q >> 3, f4 = q & 7;
            float4 v = *(const float4*)(A + (m0 + e)*HID + k0 + f4*4);
            sA[(f4*4+0)*129 + e] = v.x;
            sA[(f4*4+1)*129 + e] = v.y;
            sA[(f4*4+2)*129 + e] = v.z;
            sA[(f4*4+3)*129 + e] = v.w;
        }
        #pragma unroll
        for (int r = 0; r < 2; r++) {
            int q = t + r*256;
            int kk = q >> 4, c4 = q & 15;
            float4 v = *(const float4*)(B + (k0 + kk)*NAUG + n0 + c4*4);
            *(float4*)(&sB[kk*68 + c4*4]) = v;
        }
        __syncthreads();
        #pragma unroll
        for (int kk = 0; kk < 32; kk++) {
            ull b0 = *(const ull*)(&sB[kk*68 + tx*4]);
            ull b1 = *(const ull*)(&sB[kk*68 + tx*4 + 2]);
            const float* ar = &sA[kk*129 + ty*8];
            #pragma unroll
            for (int p = 0; p < 8; p++) {
                ull ap = pk2(ar[p]);
                fma2(acc[p][0], ap, b0);
                fma2(acc[p][1], ap, b1);
            }
        }
        __syncthreads();
    }
    if (n0 < 5*HID) {
        #pragma unroll
        for (int p = 0; p < 8; p++) {
            float* yp = g_Y + (size_t)(m0 + ty*8 + p)*NAUG + n0 + tx*4;
            *(float2*)(yp)     = up2(acc[p][0]);
            *(float2*)(yp + 2) = up2(acc[p][1]);
        }
    } else {
        int ob = n0 - 5*HID + tx*4;
        float c0 = cb[ob], c1 = cb[ob+1], c2 = cb[ob+2], c3 = cb[ob+3];
        #pragma unroll
        for (int p = 0; p < 8; p++) {
            float* hp = g_h + (size_t)(m0 + ty*8 + p)*HID + ob;
            float2 v0 = up2(acc[p][0]);
            float2 v1 = up2(acc[p][1]);
            float r0 = v0.x + c0, r1 = v0.y + c1, r2 = v1.x + c2, r3 = v1.y + c3;
            if (resid) { r0 += hp[0]; r1 += hp[1]; r2 += hp[2]; r3 += hp[3]; }
            hp[0] = r0; hp[1] = r1; hp[2] = r2; hp[3] = r3;
        }
    }
}

// ---------------- per-edge combine + scatter: h[dst] += sum_k coef_k * Y[src, k*192+o] ----------------
__global__ void k_escatter(const int* __restrict__ ei, const float* __restrict__ attr) {
    int e = blockIdx.x;            // 2048 blocks
    int o = threadIdx.x;           // 192
    int s = ei[e], d = ei[EE + e];
    float4 a = __ldg((const float4*)(attr + e*4));
    const float* Ys = g_Y + (size_t)s*NAUG;
    float v = Ys[4*HID + o]
            + a.x*Ys[o] + a.y*Ys[HID + o] + a.z*Ys[2*HID + o] + a.w*Ys[3*HID + o];
    atomicAdd(&g_h[d*HID + o], v);
}

// ---------------- final linear ----------------
__global__ void k_out(const float* __restrict__ ow, const float* __restrict__ ob,
                      float* __restrict__ out) {
    int t = blockIdx.x*blockDim.x + threadIdx.x;
    if (t >= NN*2) return;
    int n = t >> 1, oc = t & 1;
    float acc = ob[oc];
    for (int j = 0; j < HID; j++)
        acc += g_z[n*HID + j] * ow[j*2 + oc];
    out[n*2 + oc] = acc;
}

// ---------------- launcher ----------------
extern "C" void kernel_launch(void* const* d_in, const int* in_sizes, int n_in,
                              void* d_out, int out_size) {
    const float* x       = (const float*)d_in[0];
    const int*   ei      = (const int*)  d_in[1];
    const float* attr    = (const float*)d_in[2];
    const float* cheb_w  = (const float*)d_in[4];
    const float* cheb_b  = (const float*)d_in[5];
    const float* eenc_w  = (const float*)d_in[6];
    const float* eenc_b  = (const float*)d_in[7];
    const float* nn1_w   = (const float*)d_in[8];
    const float* nn1_b   = (const float*)d_in[9];
    const float* nn2_w   = (const float*)d_in[10];
    const float* nn2_b   = (const float*)d_in[11];
    const float* root_w  = (const float*)d_in[12];
    const float* conv_b  = (const float*)d_in[13];
    const float* ln_g    = (const float*)d_in[14];
    const float* ln_b    = (const float*)d_in[15];
    const float* out_w   = (const float*)d_in[16];
    const float* out_b   = (const float*)d_in[17];
    float* out = (float*)d_out;

    // edge-MLP linearization (graph-independent)
    k_G<<<NL, HID>>>(eenc_w, eenc_b, nn1_w, nn1_b);
    k_M<<<dim3(36, NL), 256>>>(nn2_w, nn2_b);
    k_root<<<144, 256>>>(root_w);

    // degree / normalization + Cheb scatters
    k_zero<<<68, 256>>>();
    k_deg<<<8, 256>>>(ei);
    k_dinv<<<4, 256>>>();
    for (int k = 1; k < KCH; k++)
        k_scat<<<32, 256>>>(ei, x, k);
    k_cheb_out<<<NN, HID>>>(x, cheb_w, cheb_b);

    // 4 NNConv layers
    for (int i = 0; i < NL; i++) {
        if (i > 0) k_ln_relu<<<NN, HID>>>(ln_g + i*HID, ln_b + i*HID);
        k_gemm<<<dim3(8, 18), 256>>>(i, i > 0 ? 1 : 0, conv_b + i*HID);
        k_escatter<<<EE, HID>>>(ei, attr);
    }

    // final norm + head
    k_ln_relu<<<NN, HID>>>(ln_g, ln_b);
    k_out<<<8, 256>>>(out_w, out_b, out);
}